// round 13
// baseline (speedup 1.0000x reference)
#include <cuda_runtime.h>

// NeRF fused render — TWO RAYS PER WARP (16 lanes per ray).
// Warp-wide work (prologue, scans, scatter, reduction) serves 2 rays in the
// same issue slots; scans are width-16 (4 steps). Lane owns 8 blocked samples
// of its ray. Compositing via exp-difference (one additive width-16 scan).
// CDF intervals quad-owned per lane (float4 load, no neighbor shuffles).
// rcp.approx divisions; streaming cache hints; all global I/O 128-bit exact.
// NOTE (measured): redux.sync is INT-ONLY on sm_103a; L2 prefetch is neutral.

constexpr int T0 = 64;     // coarse intervals
constexpr int TF = 128;    // fine samples
constexpr int OUTW = 4 + 3 * TF;      // 388 floats per ray
constexpr int WPB = 8;                // warps per block
constexpr int RPB = WPB * 2;          // rays per block = 16
constexpr unsigned FULL = 0xffffffffu;

__device__ __forceinline__ float frcp(float x) {
    float r;
    asm("rcp.approx.f32 %0, %1;" : "=f"(r) : "f"(x));
    return r;
}

__device__ __forceinline__ void contract_pt(float zm,
                                            float ox, float oy, float oz,
                                            float dx, float dy, float dz,
                                            float& cx, float& cy, float& cz)
{
    float x = fmaf(dx, zm, ox);
    float y = fmaf(dy, zm, oy);
    float z = fmaf(dz, zm, oz);
    const float ax = fabsf(x), ay = fabsf(y), az = fabsf(z);
    const float mag = fmaxf(ax, fmaxf(ay, az));
    cx = x; cy = y; cz = z;
    if (mag >= 1.0f) {
        const float im = frcp(mag);
        const float sm = (2.0f - im) * im;
        cx = x * im; cy = y * im; cz = z * im;
        if (ax == mag)      cx = x * sm;   // argmax tie-break order x,y,z
        else if (ay == mag) cy = y * sm;
        else                cz = z * sm;
    }
}

__global__ __launch_bounds__(WPB * 32, 5)
void nerf_render_kernel(const float* __restrict__ rays_o,
                        const float* __restrict__ rays_d,
                        const float* __restrict__ aabb,
                        const float* __restrict__ wc,     // [N, 64]
                        const float* __restrict__ sigmas, // [N, 128]
                        const float* __restrict__ rgbs,   // [N, 128, 3]
                        float* __restrict__ out,          // [N, 388]
                        int N)
{
    __shared__ __align__(16) float s_zed[RPB][TF + 8];   // 129 edges per ray

    const int warp = threadIdx.x >> 5;
    const int lane = threadIdx.x & 31;
    const int sub  = lane & 15;          // lane within the ray's 16-lane group
    const int half = lane >> 4;
    const int ray  = blockIdx.x * RPB + 2 * warp + half;
    if (ray >= N) return;

    // ---- ray + aabb (uniform within each 16-lane half) ----
    const float ox = rays_o[3 * ray + 0];
    const float oy = rays_o[3 * ray + 1];
    const float oz = rays_o[3 * ray + 2];
    const float dx = rays_d[3 * ray + 0];
    const float dy = rays_d[3 * ray + 1];
    const float dz = rays_d[3 * ray + 2];

    const float ix = frcp(dx + 1e-15f);
    const float iy = frcp(dy + 1e-15f);
    const float iz = frcp(dz + 1e-15f);
    const float t0x = (aabb[0] - ox) * ix, t1x = (aabb[3] - ox) * ix;
    const float t0y = (aabb[1] - oy) * iy, t1y = (aabb[4] - oy) * iy;
    const float t0z = (aabb[2] - oz) * iz, t1z = (aabb[5] - oz) * iz;

    float nearv = fmaxf(fmaxf(fminf(t0x, t1x), fminf(t0y, t1y)), fminf(t0z, t1z));
    float farv  = fminf(fminf(fmaxf(t0x, t1x), fmaxf(t0y, t1y)), fmaxf(t0z, t1z));
    if (farv < nearv) { nearv = 1e9f; farv = 1e9f; }
    nearv = fmaxf(nearv, 0.05f);
    const float span = farv - nearv;
    const float db = span * (1.0f / 64.0f);   // coarse bin width

    // ---- CDF: lane owns weights {4s..4s+3} -> intervals 4s..4s+3 local ----
    const float4 wq = __ldcs(reinterpret_cast<const float4*>(
        wc + (size_t)ray * T0 + 4 * sub));
    const float wa = wq.x + 0.01f;
    const float wb = wq.y + 0.01f;
    const float wcv = wq.z + 0.01f;
    const float wd = wq.w + 0.01f;
    const float pA = wa;
    const float pB = pA + wb;
    const float pC = pB + wcv;
    const float quad = pC + wd;

    float incl = quad;
    #pragma unroll
    for (int o = 1; o < 16; o <<= 1) {
        float v = __shfl_up_sync(FULL, incl, o, 16);
        if (sub >= o) incl += v;
    }
    float excl = __shfl_up_sync(FULL, incl, 1, 16);
    if (sub == 0) excl = 0.0f;
    const float inv_tot = frcp(__shfl_sync(FULL, incl, 15, 16));

    const float cs0 = fminf(excl * inv_tot, 1.0f);          // C[4s]
    const float cs1 = fminf((excl + pA) * inv_tot, 1.0f);   // C[4s+1]
    const float cs2 = fminf((excl + pB) * inv_tot, 1.0f);   // C[4s+2]
    const float cs3 = fminf((excl + pC) * inv_tot, 1.0f);   // C[4s+3]
    const float cs4 = fminf(incl * inv_tot, 1.0f);          // C[4s+4]
    const float cs[5] = {cs0, cs1, cs2, cs3, cs4};

    float* zed = s_zed[2 * warp + half];

    // ---- scatter fine edges: interval k covers u in [C[k], C[k+1]) ----
    constexpr float inv129 = 1.0f / 129.0f;
    #pragma unroll
    for (int h = 0; h < 4; ++h) {
        const int k = 4 * sub + h;
        const float a = cs[h];
        const float b = cs[h + 1];

        int j0 = (int)ceilf(fmaf(129.0f, a, -0.5f));
        int j1 = (k == 63) ? 129 : (int)ceilf(fmaf(129.0f, b, -0.5f));
        j0 = max(j0, 0);
        j1 = min(j1, 129);

        const float inv_den = frcp(fmaxf(b - a, 1e-12f));
        const float b0 = fmaf(db, (float)k, nearv);
        const float stepz = inv_den * inv129 * db;
        const float zmax = b0 + db;
        float zval = fmaf(fmaf((float)j0 + 0.5f, inv129, -a) * inv_den, db, b0);

        for (int j = j0; j < j1; ++j) {
            zed[j] = fminf(zval, zmax);   // t >= 0 guaranteed at j0, increasing
            zval += stepz;
        }
    }
    __syncwarp();

    // ---- blocked compositing: lane owns samples 8s..8s+7 ----
    const int s8 = 8 * sub;
    const float4 za = *reinterpret_cast<const float4*>(&zed[s8]);
    const float4 zb = *reinterpret_cast<const float4*>(&zed[s8 + 4]);
    const float e8 = zed[s8 + 8];

    const float* sgp = sigmas + (size_t)ray * TF + s8;
    const float4 sgA = __ldcs(reinterpret_cast<const float4*>(sgp));
    const float4 sgB = __ldcs(reinterpret_cast<const float4*>(sgp + 4));

    const float q0 = sgA.x * (za.y - za.x);
    const float q1 = sgA.y * (za.z - za.y);
    const float q2 = sgA.z * (za.w - za.z);
    const float q3 = sgA.w * (zb.x - za.w);
    const float q4 = sgB.x * (zb.y - zb.x);
    const float q5 = sgB.y * (zb.z - zb.y);
    const float q6 = sgB.z * (zb.w - zb.z);
    const float q7 = sgB.w * (e8   - zb.w);

    const float p1 = q0;
    const float p2 = p1 + q1;
    const float p3 = p2 + q2;
    const float p4 = p3 + q3;
    const float p5 = p4 + q4;
    const float p6 = p5 + q5;
    const float p7 = p6 + q6;
    const float Tl = p7 + q7;             // lane-local optical depth

    float iS = Tl;
    #pragma unroll
    for (int o = 1; o < 16; o <<= 1) {
        float v = __shfl_up_sync(FULL, iS, o, 16);
        if (sub >= o) iS += v;
    }
    float S0 = __shfl_up_sync(FULL, iS, 1, 16);
    if (sub == 0) S0 = 0.0f;

    const float E0 = __expf(-S0);
    const float E1 = __expf(-(S0 + p1));
    const float E2 = __expf(-(S0 + p2));
    const float E3 = __expf(-(S0 + p3));
    const float E4 = __expf(-(S0 + p4));
    const float E5 = __expf(-(S0 + p5));
    const float E6 = __expf(-(S0 + p6));
    const float E7 = __expf(-(S0 + p7));
    const float E8 = __expf(-(S0 + Tl));

    const float w0 = E0 - E1, w1 = E1 - E2, w2 = E2 - E3, w3 = E3 - E4;
    const float w4 = E4 - E5, w5 = E5 - E6, w6 = E6 - E7, w7 = E7 - E8;

    const float zm0 = 0.5f * (za.x + za.y);
    const float zm1 = 0.5f * (za.y + za.z);
    const float zm2 = 0.5f * (za.z + za.w);
    const float zm3 = 0.5f * (za.w + zb.x);
    const float zm4 = 0.5f * (zb.x + zb.y);
    const float zm5 = 0.5f * (zb.y + zb.z);
    const float zm6 = 0.5f * (zb.z + zb.w);
    const float zm7 = 0.5f * (zb.w + e8);

    float dep = w0 * zm0 + w1 * zm1 + w2 * zm2 + w3 * zm3
              + w4 * zm4 + w5 * zm5 + w6 * zm6 + w7 * zm7;

    // ---- contraction + packed xyz streaming stores (6x STG.128) ----
    const size_t base = (size_t)ray * OUTW;
    float4* xo4 = reinterpret_cast<float4*>(out + base + 4) + 6 * sub;
    {
        float a0x,a0y,a0z, a1x,a1y,a1z, a2x,a2y,a2z, a3x,a3y,a3z;
        contract_pt(zm0, ox,oy,oz, dx,dy,dz, a0x,a0y,a0z);
        contract_pt(zm1, ox,oy,oz, dx,dy,dz, a1x,a1y,a1z);
        contract_pt(zm2, ox,oy,oz, dx,dy,dz, a2x,a2y,a2z);
        contract_pt(zm3, ox,oy,oz, dx,dy,dz, a3x,a3y,a3z);
        __stcs(xo4 + 0, make_float4(a0x, a0y, a0z, a1x));
        __stcs(xo4 + 1, make_float4(a1y, a1z, a2x, a2y));
        __stcs(xo4 + 2, make_float4(a2z, a3x, a3y, a3z));
    }
    {
        float a4x,a4y,a4z, a5x,a5y,a5z, a6x,a6y,a6z, a7x,a7y,a7z;
        contract_pt(zm4, ox,oy,oz, dx,dy,dz, a4x,a4y,a4z);
        contract_pt(zm5, ox,oy,oz, dx,dy,dz, a5x,a5y,a5z);
        contract_pt(zm6, ox,oy,oz, dx,dy,dz, a6x,a6y,a6z);
        contract_pt(zm7, ox,oy,oz, dx,dy,dz, a7x,a7y,a7z);
        __stcs(xo4 + 3, make_float4(a4x, a4y, a4z, a5x));
        __stcs(xo4 + 4, make_float4(a5y, a5z, a6x, a6y));
        __stcs(xo4 + 5, make_float4(a6z, a7x, a7y, a7z));
    }

    // ---- rgb: 6x LDG.128 streaming, compile-time channel mapping ----
    const float4* rg4 = reinterpret_cast<const float4*>(
        rgbs + (size_t)ray * TF * 3) + 6 * sub;
    float img0, img1, img2;
    {
        const float4 f0 = __ldcs(rg4 + 0);
        const float4 f1 = __ldcs(rg4 + 1);
        const float4 f2 = __ldcs(rg4 + 2);
        img0 = w0 * f0.x + w1 * f0.w + w2 * f1.z + w3 * f2.y;
        img1 = w0 * f0.y + w1 * f1.x + w2 * f1.w + w3 * f2.z;
        img2 = w0 * f0.z + w1 * f1.y + w2 * f2.x + w3 * f2.w;
    }
    {
        const float4 f3 = __ldcs(rg4 + 3);
        const float4 f4 = __ldcs(rg4 + 4);
        const float4 f5 = __ldcs(rg4 + 5);
        img0 += w4 * f3.x + w5 * f3.w + w6 * f4.z + w7 * f5.y;
        img1 += w4 * f3.y + w5 * f4.x + w6 * f4.w + w7 * f5.z;
        img2 += w4 * f3.z + w5 * f4.y + w6 * f5.x + w7 * f5.w;
    }

    // ---- width-16 transposed reduction (serves both rays at once) ----
    #pragma unroll
    for (int o = 8; o >= 4; o >>= 1) {
        img0 += __shfl_down_sync(FULL, img0, o, 16);
        img1 += __shfl_down_sync(FULL, img1, o, 16);
        img2 += __shfl_down_sync(FULL, img2, o, 16);
        dep  += __shfl_down_sync(FULL, dep,  o, 16);
    }
    // partials in subs 0..3; lane (4q + r) fetches quantity q from sub r
    const int src = sub & 3;
    const float a0 = __shfl_sync(FULL, img0, src, 16);
    const float a1 = __shfl_sync(FULL, img1, src, 16);
    const float a2 = __shfl_sync(FULL, img2, src, 16);
    const float a3 = __shfl_sync(FULL, dep,  src, 16);
    const int q = sub >> 2;
    float m = (q == 0) ? a0 : (q == 1) ? a1 : (q == 2) ? a2 : a3;
    m += __shfl_down_sync(FULL, m, 2, 16);
    m += __shfl_down_sync(FULL, m, 1, 16);
    if (src == 0)
        __stcs(out + base + q, m);   // 4 lanes per ray, one 16B segment each
}

extern "C" void kernel_launch(void* const* d_in, const int* in_sizes, int n_in,
                              void* d_out, int out_size)
{
    const float* rays_o = (const float*)d_in[0];
    const float* rays_d = (const float*)d_in[1];
    const float* aabb   = (const float*)d_in[2];
    const float* wc     = (const float*)d_in[3];
    const float* sigmas = (const float*)d_in[4];
    const float* rgbs   = (const float*)d_in[5];
    float* out = (float*)d_out;

    const int N = in_sizes[0] / 3;   // rays_o has N*3 elements
    const int blocks = (N + RPB - 1) / RPB;
    nerf_render_kernel<<<blocks, WPB * 32>>>(
        rays_o, rays_d, aabb, wc, sigmas, rgbs, out, N);
}